// round 13
// baseline (speedup 1.0000x reference)
#include <cuda_runtime.h>
#include <stdint.h>
#include <math.h>

#define BB 32
#define TT 256
#define INS 64
#define HH 128
#define G4 512
#define EPSV 1e-7f

typedef unsigned long long u64;
typedef unsigned int u32;

// ---- static device scratch (no cudaMalloc allowed) ----
__device__ __align__(16) u64 g_whp[32 * 512 * 2];   // W_hh packed: [k4][j] -> float4 as 2x u64
__device__ float g_gx[BB * TT * G4];                // precomputed input gate contributions

__device__ __forceinline__ u64 ffma2(u64 a, u64 b, u64 c) {
    u64 d;
    asm("fma.rn.f32x2 %0, %1, %2, %3;" : "=l"(d) : "l"(a), "l"(b), "l"(c));
    return d;
}
__device__ __forceinline__ float f2sum(u64 v) {
    float2 f = *reinterpret_cast<float2*>(&v);
    return f.x + f.y;
}
// accuracy-safe nonlinearities (tanh.approx fails the attn_w check: R10)
__device__ __forceinline__ float fsig(float x)  { return 1.0f / (1.0f + __expf(-x)); }
__device__ __forceinline__ float ftanh(float x) { return 2.0f / (1.0f + __expf(-2.0f * x)) - 1.0f; }

__device__ __forceinline__ u32 smem_u32(const void* p) {
    u32 a;
    asm("{ .reg .u64 t; cvta.to.shared.u64 t, %1; cvt.u32.u64 %0, t; }" : "=r"(a) : "l"(p));
    return a;
}

__device__ __forceinline__ void mbar_wait(u32 mb, u32 parity) {
    asm volatile(
        "{\n\t"
        ".reg .pred P;\n\t"
        "WL_%=:\n\t"
        "mbarrier.try_wait.parity.acquire.cta.shared::cta.b64 P, [%0], %1, 0x989680;\n\t"
        "@P bra.uni WD_%=;\n\t"
        "bra.uni WL_%=;\n\t"
        "WD_%=:\n\t"
        "}"
        :: "r"(mb), "r"(parity) : "memory");
}

// ---------------- fused pack + gx kernel ----------------
__global__ __launch_bounds__(512) void gxpack_kernel(const float* __restrict__ x,
                                                     const float* __restrict__ W_ih,
                                                     const float* __restrict__ W_hh,
                                                     const float* __restrict__ b_ih,
                                                     const float* __restrict__ b_hh) {
    int b = blockIdx.x, ty = blockIdx.y, j = threadIdx.x;

    if (ty == 0) {
        float* whp = (float*)g_whp;
        for (int idx = b * 512 + j; idx < G4 * HH; idx += 32 * 512) {
            int r = idx >> 7, k = idx & 127;
            whp[((k >> 2) * 512 + r) * 4 + (k & 3)] = W_hh[idx];
        }
    }

    __shared__ float xs[16][INS];
    int t0 = ty * 16;
    for (int idx = j; idx < 16 * INS; idx += 512)
        xs[idx >> 6][idx & 63] = x[(b * TT + t0 + (idx >> 6)) * INS + (idx & 63)];

    float4 w[16];
    const float4* wr = (const float4*)(W_ih + j * INS);
#pragma unroll
    for (int k4 = 0; k4 < 16; k4++) w[k4] = wr[k4];
    float bs = b_ih[j] + b_hh[j];
    __syncthreads();

    for (int tt = 0; tt < 16; tt++) {
        float acc = bs;
#pragma unroll
        for (int k4 = 0; k4 < 16; k4++) {
            acc = fmaf(w[k4].x, xs[tt][4 * k4 + 0], acc);
            acc = fmaf(w[k4].y, xs[tt][4 * k4 + 1], acc);
            acc = fmaf(w[k4].z, xs[tt][4 * k4 + 2], acc);
            acc = fmaf(w[k4].w, xs[tt][4 * k4 + 3], acc);
        }
        g_gx[(b * TT + t0 + tt) * G4 + j] = acc;
    }
}

// ---------------- recurrent kernel: cluster of 2 CTAs per TWO batch rows ----------------
// 544 threads: warps 0-15 GEMV k-half for BOTH rows (register weights shared);
// warps 8-11 also run row-0 tail, warps 12-15 row-1 tail (replicated in both CTAs);
// warp 16 = scheduler (expect_tx + top-5 for both rows). One mbarrier per parity
// counts all 8192 bytes (2 rows x 2 CTAs x 512 floats).
__global__ __launch_bounds__(544) void rec_kernel(const float* __restrict__ w_t,
                                                  float* __restrict__ out) {
    int tid = threadIdx.x, lane = tid & 31;
    int cl = blockIdx.x >> 1;          // cluster id: rows 2*cl, 2*cl+1
    int b0 = cl * 2;

    u32 rank;
    asm("mov.u32 %0, %%cluster_ctarank;" : "=r"(rank));
    u32 peer = rank ^ 1u;

    __shared__ __align__(16) float h_sh[2][HH];
    __shared__ float gpart[2][2][2][G4];           // [parity][row][khalf][gate] (16 KB)
    __shared__ float pbv[2][HH];
    __shared__ __align__(16) float slots[2][5][HH];
    __shared__ float redA[2][4];
    __shared__ float sb_arr[2][8];
    __shared__ float top5v[2][5];
    __shared__ int   top5r[2][5];
    __shared__ int   top5s[2][5];
    __shared__ int   rowslot[2][5];
    __shared__ int   evslot[2];
    __shared__ float wa_s[HH], wb_s[HH];
    __shared__ __align__(8) u64 mbar[2];

    float* out_c = out;             // [B,H]
    float* out_w = out + BB * HH;   // [B,T]
    const float* gxb0 = g_gx + (size_t)b0 * TT * G4;
    const float* gxb1 = gxb0 + TT * G4;

    if (tid < HH) {
        h_sh[0][tid] = 0.0f; h_sh[1][tid] = 0.0f;
        slots[0][0][tid] = 0.0f; slots[1][0][tid] = 0.0f;
        wa_s[tid] = w_t[tid];
        wb_s[tid] = w_t[HH + tid];
    }
    if (tid == 0) {
        for (int r = 0; r < 2; r++) {
            sb_arr[r][0] = 0.0f;
            top5v[r][0] = 0.0f; top5r[r][0] = 0; top5s[r][0] = 0;
            for (int q = 1; q < 5; q++) { top5v[r][q] = -1e30f; top5r[r][q] = -1; top5s[r][q] = q; }
            rowslot[r][0] = 0;
            evslot[r] = -1;
        }
        asm volatile("mbarrier.init.shared.b64 [%0], 1;" :: "r"(smem_u32(&mbar[0])) : "memory");
        asm volatile("mbarrier.init.shared.b64 [%0], 1;" :: "r"(smem_u32(&mbar[1])) : "memory");
    }
    if (tid < TT) out_w[(b0 + (int)rank) * TT + tid] = 0.0f;  // rank r zeroes row b0+r

    // cluster-space base addresses (offsets: parity*8192, row*4096, +tid*4; mbar +parity*8)
    u32 mb = smem_u32(&mbar[0]);
    u32 gl = smem_u32(&gpart[0][0][rank][0]);
    u32 sl, smb, gr, rmb;
    asm("mapa.shared::cluster.u32 %0, %1, %2;" : "=r"(sl)  : "r"(gl), "r"(rank));
    asm("mapa.shared::cluster.u32 %0, %1, %2;" : "=r"(smb) : "r"(mb), "r"(rank));
    asm("mapa.shared::cluster.u32 %0, %1, %2;" : "=r"(gr)  : "r"(gl), "r"(peer));
    asm("mapa.shared::cluster.u32 %0, %1, %2;" : "=r"(rmb) : "r"(mb), "r"(peer));

    float c_reg = 0.0f, ac = 0.0f;
    u32 ph0 = 0, ph1 = 0;            // per-buffer wait parity (flips once per USE)

    ulonglong2 wc[16];
    float gxv0 = 0.0f, gxv1 = 0.0f;
    if (tid < 512) {
        const ulonglong2* wp = (const ulonglong2*)g_whp;
#pragma unroll
        for (int k4 = 0; k4 < 16; k4++) wc[k4] = wp[(rank * 16 + k4) * 512 + tid];
        if (rank == 0) { gxv0 = gxb0[tid]; gxv1 = gxb1[tid]; }
    }

    __syncthreads();
    asm volatile("barrier.cluster.arrive.aligned;" ::: "memory");
    asm volatile("barrier.cluster.wait.aligned;"   ::: "memory");

    for (int i = 0; i < TT; i++) {
        int p = i & 1;
        u32 poff = (u32)p * 8192u;
        u32 lmb = smb + (u32)p * 8u;
        u32 pmb = rmb + (u32)p * 8u;

        if (tid < 512) {
            // ---- GEMV for both rows (shared register weights) ----
            const ulonglong2* h20 = (const ulonglong2*)h_sh[0];
            const ulonglong2* h21 = (const ulonglong2*)h_sh[1];
            {
                u64 a0 = 0ull, a1 = 0ull, a2 = 0ull, a3 = 0ull;
#pragma unroll
                for (int k4 = 0; k4 < 16; k4++) {
                    ulonglong2 w = wc[k4];
                    ulonglong2 hv = h20[rank * 16 + k4];
                    if (k4 & 1) { a2 = ffma2(w.x, hv.x, a2); a3 = ffma2(w.y, hv.y, a3); }
                    else        { a0 = ffma2(w.x, hv.x, a0); a1 = ffma2(w.y, hv.y, a1); }
                }
                float part = gxv0 + (f2sum(a0) + f2sum(a1)) + (f2sum(a2) + f2sum(a3));
                u32 off = poff + tid * 4u;
                asm volatile("st.async.shared::cluster.mbarrier::complete_tx::bytes.f32 [%0], %1, [%2];"
                             :: "r"(sl + off), "f"(part), "r"(lmb) : "memory");
                asm volatile("st.async.shared::cluster.mbarrier::complete_tx::bytes.f32 [%0], %1, [%2];"
                             :: "r"(gr + off), "f"(part), "r"(pmb) : "memory");
            }
            {
                u64 a0 = 0ull, a1 = 0ull, a2 = 0ull, a3 = 0ull;
#pragma unroll
                for (int k4 = 0; k4 < 16; k4++) {
                    ulonglong2 w = wc[k4];
                    ulonglong2 hv = h21[rank * 16 + k4];
                    if (k4 & 1) { a2 = ffma2(w.x, hv.x, a2); a3 = ffma2(w.y, hv.y, a3); }
                    else        { a0 = ffma2(w.x, hv.x, a0); a1 = ffma2(w.y, hv.y, a1); }
                }
                float part = gxv1 + (f2sum(a0) + f2sum(a1)) + (f2sum(a2) + f2sum(a3));
                u32 off = poff + 4096u + tid * 4u;
                asm volatile("st.async.shared::cluster.mbarrier::complete_tx::bytes.f32 [%0], %1, [%2];"
                             :: "r"(sl + off), "f"(part), "r"(lmb) : "memory");
                asm volatile("st.async.shared::cluster.mbarrier::complete_tx::bytes.f32 [%0], %1, [%2];"
                             :: "r"(gr + off), "f"(part), "r"(pmb) : "memory");
            }
            if (rank == 0 && i + 1 < TT) {
                gxv0 = gxb0[(i + 1) * G4 + tid];
                gxv1 = gxb1[(i + 1) * G4 + tid];
            }

            if (tid >= 256) {
                // ---- tail: warps 8-11 -> row 0, warps 12-15 -> row 1 ----
                int row = (tid >> 7) - 2;        // 256..383 -> 0, 384..511 -> 1
                int j = tid & 127;
                int wrp2 = (tid >> 5) & 3;

                asm volatile("bar.sync 2, 288;" ::: "memory");   // scheduler results ready
                int ev = evslot[row];
                if (ev >= 0) slots[row][ev][j] = h_sh[row][j];   // row i = h(i-1)

                // wait on this parity's buffer; per-buffer phase flips once per use
                if (p) { mbar_wait(mb + 8u, ph1); ph1 ^= 1u; }
                else   { mbar_wait(mb,      ph0); ph0 ^= 1u; }

                const float* gp0 = &gpart[p][row][0][0];
                const float* gp1 = &gpart[p][row][1][0];
                float ti = fsig (gp0[j]          + gp1[j]);
                float tf = fsig (gp0[HH + j]     + gp1[HH + j]);
                float tg = ftanh(gp0[2*HH + j]   + gp1[2*HH + j]);
                float to = fsig (gp0[3*HH + j]   + gp1[3*HH + j]);
                c_reg = tf * c_reg + ti * tg;
                float hl = to * ftanh(c_reg);

                float wv[5]; int ws[5];
                if (i < 5) {
                    float pa = ftanh(hl) * wa_s[j];
#pragma unroll
                    for (int o = 16; o; o >>= 1) pa += __shfl_xor_sync(0xffffffffu, pa, o);
                    if (lane == 0) redA[row][wrp2] = pa;
                    if (row == 0) asm volatile("bar.sync 3, 128;" ::: "memory");
                    else          asm volatile("bar.sync 4, 128;" ::: "memory");
                    float ta = redA[row][0] + redA[row][1] + redA[row][2] + redA[row][3];
                    int rem = i + 1;
#pragma unroll
                    for (int r = 0; r < 5; r++) {
                        if (r < rem) { wv[r] = ta + sb_arr[row][r]; ws[r] = rowslot[row][r]; }
                        else         { wv[r] = 0.0f;                ws[r] = 0; }
                    }
                } else {
                    float d = top5v[row][4] + EPSV;
                    float ssum = 0.0f;
#pragma unroll
                    for (int q = 0; q < 5; q++) {
                        float v = fmaxf(top5v[row][q] - d, 0.0f);
                        wv[q] = v; ws[q] = top5s[row][q];
                        ssum += v;
                    }
                    float inv = 1.0f / (ssum + EPSV);
#pragma unroll
                    for (int q = 0; q < 5; q++) wv[q] *= inv;
                }
                ac = 0.0f;
#pragma unroll
                for (int q = 0; q < 5; q++) ac = fmaf(wv[q], slots[row][ws[q]][j], ac);
                float hf = hl + ac;
                h_sh[row][j] = hf;
                pbv[row][j] = ftanh(hf) * wb_s[j];
            }
        } else {
            // ---- warp 16: expect_tx + top-5 maintenance for both rows ----
            if (lane == 0) {
                asm volatile("mbarrier.arrive.expect_tx.shared.b64 _, [%0], %1;"
                             :: "r"(mb + (u32)p * 8u), "r"(8192u) : "memory");
            }
            if (i > 0) {
#pragma unroll
                for (int r = 0; r < 2; r++) {
                    float s = pbv[r][lane] + pbv[r][lane + 32] + pbv[r][lane + 64] + pbv[r][lane + 96];
#pragma unroll
                    for (int o = 16; o; o >>= 1) s += __shfl_xor_sync(0xffffffffu, s, o);
                    if (lane == 0) {
                        float sbn = s;
                        if (i < 5) sb_arr[r][i] = sbn;
                        if (sbn > top5v[r][4]) {
                            int evs = top5s[r][4];
                            int q = 4;
                            while (q > 0 && sbn > top5v[r][q - 1]) {
                                top5v[r][q] = top5v[r][q - 1];
                                top5r[r][q] = top5r[r][q - 1];
                                top5s[r][q] = top5s[r][q - 1];
                                q--;
                            }
                            top5v[r][q] = sbn; top5r[r][q] = i; top5s[r][q] = evs;
                            if (i < 5) rowslot[r][i] = evs;
                            evslot[r] = evs;
                        } else evslot[r] = -1;
                    }
                }
            }
            asm volatile("bar.sync 2, 288;" ::: "memory");
        }
        __syncthreads();  // step boundary: h_sh/pbv stable for next step
    }

    // ---- epilogue: rank r writes row b0+r (both CTAs hold replicated results) ----
    {
        int myrow = (int)rank;
        int bme = b0 + myrow;
        if (tid >= 256 + myrow * 128 && tid < 384 + myrow * 128)
            out_c[bme * HH + (tid & 127)] = ac;
        if (tid == 0) {
            float d = top5v[myrow][4] + EPSV;
            float ssum = 0.0f, v[5];
#pragma unroll
            for (int q = 0; q < 5; q++) { v[q] = fmaxf(top5v[myrow][q] - d, 0.0f); ssum += v[q]; }
            float inv = 1.0f / (ssum + EPSV);
#pragma unroll
            for (int q = 0; q < 5; q++)
                if (v[q] > 0.0f) out_w[bme * TT + top5r[myrow][q]] = v[q] * inv;
        }
    }
    asm volatile("barrier.cluster.arrive.aligned;" ::: "memory");
    asm volatile("barrier.cluster.wait.aligned;"   ::: "memory");
}

extern "C" void kernel_launch(void* const* d_in, const int* in_sizes, int n_in,
                              void* d_out, int out_size) {
    const float* x    = (const float*)d_in[0];
    const float* W_ih = (const float*)d_in[1];
    const float* W_hh = (const float*)d_in[2];
    const float* b_ih = (const float*)d_in[3];
    const float* b_hh = (const float*)d_in[4];
    const float* w_t  = (const float*)d_in[5];
    float* out = (float*)d_out;

    gxpack_kernel<<<dim3(BB, TT / 16), 512>>>(x, W_ih, W_hh, b_ih, b_hh);

    cudaLaunchConfig_t cfg = {};
    cfg.gridDim  = dim3(BB, 1, 1);      // 32 CTAs = 16 clusters x 2, each cluster = 2 rows
    cfg.blockDim = dim3(544, 1, 1);
    cfg.dynamicSmemBytes = 0;
    cfg.stream = 0;
    cudaLaunchAttribute attrs[1];
    attrs[0].id = cudaLaunchAttributeClusterDimension;
    attrs[0].val.clusterDim.x = 2;
    attrs[0].val.clusterDim.y = 1;
    attrs[0].val.clusterDim.z = 1;
    cfg.attrs = attrs;
    cfg.numAttrs = 1;
    cudaLaunchKernelEx(&cfg, rec_kernel, w_t, out);
}

// round 14
// speedup vs baseline: 1.1691x; 1.1691x over previous
#include <cuda_runtime.h>
#include <stdint.h>
#include <math.h>

#define BB 32
#define TT 256
#define INS 64
#define HH 128
#define G4 512
#define HHF 64
#define EPSV 1e-7f

typedef unsigned long long u64;
typedef unsigned int u32;

// ---- static device scratch (no cudaMalloc allowed) ----
__device__ __align__(16) u64 g_whp[32 * 512 * 2];   // W_hh packed: [k4][row] -> float4 as 2x u64
__device__ float g_gx[BB * TT * G4];                // precomputed input gate contributions

__device__ __forceinline__ u64 ffma2(u64 a, u64 b, u64 c) {
    u64 d;
    asm("fma.rn.f32x2 %0, %1, %2, %3;" : "=l"(d) : "l"(a), "l"(b), "l"(c));
    return d;
}
__device__ __forceinline__ float f2sum(u64 v) {
    float2 f = *reinterpret_cast<float2*>(&v);
    return f.x + f.y;
}
// accuracy-safe nonlinearities (tanh.approx fails the attn_w check: R10)
__device__ __forceinline__ float fsig(float x)  { return 1.0f / (1.0f + __expf(-x)); }
__device__ __forceinline__ float ftanh(float x) { return 2.0f / (1.0f + __expf(-2.0f * x)) - 1.0f; }

__device__ __forceinline__ u32 smem_u32(const void* p) {
    u32 a;
    asm("{ .reg .u64 t; cvta.to.shared.u64 t, %1; cvt.u32.u64 %0, t; }" : "=r"(a) : "l"(p));
    return a;
}

__device__ __forceinline__ void mbar_wait(u32 mb, u32 parity) {
    asm volatile(
        "{\n\t"
        ".reg .pred P;\n\t"
        "WL_%=:\n\t"
        "mbarrier.try_wait.parity.acquire.cta.shared::cta.b64 P, [%0], %1, 0x989680;\n\t"
        "@P bra.uni WD_%=;\n\t"
        "bra.uni WL_%=;\n\t"
        "WD_%=:\n\t"
        "}"
        :: "r"(mb), "r"(parity) : "memory");
}
__device__ __forceinline__ void mbar_expect(u32 mb, u32 bytes) {
    asm volatile("mbarrier.arrive.expect_tx.shared.b64 _, [%0], %1;"
                 :: "r"(mb), "r"(bytes) : "memory");
}
__device__ __forceinline__ void st_async_f32(u32 addr, float v, u32 mb) {
    asm volatile("st.async.shared::cluster.mbarrier::complete_tx::bytes.f32 [%0], %1, [%2];"
                 :: "r"(addr), "f"(v), "r"(mb) : "memory");
}

// ---------------- fused pack + gx kernel ----------------
__global__ __launch_bounds__(512) void gxpack_kernel(const float* __restrict__ x,
                                                     const float* __restrict__ W_ih,
                                                     const float* __restrict__ W_hh,
                                                     const float* __restrict__ b_ih,
                                                     const float* __restrict__ b_hh) {
    int b = blockIdx.x, ty = blockIdx.y, j = threadIdx.x;

    if (ty == 0) {
        float* whp = (float*)g_whp;
        for (int idx = b * 512 + j; idx < G4 * HH; idx += 32 * 512) {
            int r = idx >> 7, k = idx & 127;
            whp[((k >> 2) * 512 + r) * 4 + (k & 3)] = W_hh[idx];
        }
    }

    __shared__ float xs[16][INS];
    int t0 = ty * 16;
    for (int idx = j; idx < 16 * INS; idx += 512)
        xs[idx >> 6][idx & 63] = x[(b * TT + t0 + (idx >> 6)) * INS + (idx & 63)];

    float4 w[16];
    const float4* wr = (const float4*)(W_ih + j * INS);
#pragma unroll
    for (int k4 = 0; k4 < 16; k4++) w[k4] = wr[k4];
    float bs = b_ih[j] + b_hh[j];
    __syncthreads();

    for (int tt = 0; tt < 16; tt++) {
        float acc = bs;
#pragma unroll
        for (int k4 = 0; k4 < 16; k4++) {
            acc = fmaf(w[k4].x, xs[tt][4 * k4 + 0], acc);
            acc = fmaf(w[k4].y, xs[tt][4 * k4 + 1], acc);
            acc = fmaf(w[k4].z, xs[tt][4 * k4 + 2], acc);
            acc = fmaf(w[k4].w, xs[tt][4 * k4 + 3], acc);
        }
        g_gx[(b * TT + t0 + tt) * G4 + j] = acc;
    }
}

// ---------------- recurrent kernel: j-split cluster of 2 CTAs per batch row ----------------
// CTA r owns h-indices j in [64r, 64r+64): holds the 256 W_hh rows of its gates fully
// in registers (512 thr x 64 cols), computes gates LOCALLY, runs a 64-thread tail.
// Cross-CTA traffic per step: 64 hf floats (256B, mbar_h) + 2 pb partials (8B, mbar_s).
// Warps 0-7 read locally-produced h cols (no wait); warps 8-15 wait for peer hf.
__global__ __launch_bounds__(544) void rec_kernel(const float* __restrict__ w_t,
                                                  float* __restrict__ out) {
    int tid = threadIdx.x, lane = tid & 31;
    int b = blockIdx.x >> 1;

    u32 rank;
    asm("mov.u32 %0, %%cluster_ctarank;" : "=r"(rank));
    u32 peer = rank ^ 1u;

    __shared__ __align__(16) float h_sh[2][HH];    // [parity][global col]
    __shared__ float gpart[2][256];                // [colhalf][local row]
    __shared__ __align__(16) float slots[5][HHF];
    __shared__ float scal[2][2][2];                // [parity][srcCTA][warp] pb partials
    __shared__ float pasc[2][2][2];                // [parity][srcCTA][warp] pa partials
    __shared__ float sb_arr[8];
    __shared__ float top5v[5];
    __shared__ int   top5r[5], top5s[5], rowslot[5], evslot;
    __shared__ float wa_s[HHF], wb_s[HHF];
    __shared__ __align__(8) u64 mbars[6];          // h0,h1,s0,s1,pa0,pa1

    float* out_c = out;             // [B,H]
    float* out_w = out + BB * HH;   // [B,T]
    const float* gxb = g_gx + (size_t)b * TT * G4;

    if (tid < HH) { h_sh[0][tid] = 0.0f; h_sh[1][tid] = 0.0f; }
    if (tid < HHF) {
        slots[0][tid] = 0.0f;
        wa_s[tid] = w_t[(int)rank * 64 + tid];
        wb_s[tid] = w_t[HH + (int)rank * 64 + tid];
    }
    if (tid == 0) {
        sb_arr[0] = 0.0f;
        top5v[0] = 0.0f; top5r[0] = 0; top5s[0] = 0;
        for (int q = 1; q < 5; q++) { top5v[q] = -1e30f; top5r[q] = -1; top5s[q] = q; }
        rowslot[0] = 0;
        evslot = -1;
        for (int m = 0; m < 6; m++)
            asm volatile("mbarrier.init.shared.b64 [%0], 1;" :: "r"(smem_u32(&mbars[m])) : "memory");
    }
    if (rank == 0 && tid < TT) out_w[b * TT + tid] = 0.0f;

    // local mbar addresses
    u32 mbh0 = smem_u32(&mbars[0]), mbh1 = smem_u32(&mbars[1]);
    u32 mbs0 = smem_u32(&mbars[2]), mbs1 = smem_u32(&mbars[3]);
    u32 mbp0 = smem_u32(&mbars[4]), mbp1 = smem_u32(&mbars[5]);
    // peer addresses
    u32 hshl = smem_u32(&h_sh[0][0]);
    u32 scll = smem_u32(&scal[0][0][0]);
    u32 pasl = smem_u32(&pasc[0][0][0]);
    u32 r_hsh, r_scl, r_pas, r_mbh0, r_mbh1, r_mbs0, r_mbs1, r_mbp0, r_mbp1;
    asm("mapa.shared::cluster.u32 %0, %1, %2;" : "=r"(r_hsh)  : "r"(hshl), "r"(peer));
    asm("mapa.shared::cluster.u32 %0, %1, %2;" : "=r"(r_scl)  : "r"(scll), "r"(peer));
    asm("mapa.shared::cluster.u32 %0, %1, %2;" : "=r"(r_pas)  : "r"(pasl), "r"(peer));
    asm("mapa.shared::cluster.u32 %0, %1, %2;" : "=r"(r_mbh0) : "r"(mbh0), "r"(peer));
    asm("mapa.shared::cluster.u32 %0, %1, %2;" : "=r"(r_mbh1) : "r"(mbh1), "r"(peer));
    asm("mapa.shared::cluster.u32 %0, %1, %2;" : "=r"(r_mbs0) : "r"(mbs0), "r"(peer));
    asm("mapa.shared::cluster.u32 %0, %1, %2;" : "=r"(r_mbs1) : "r"(mbs1), "r"(peer));
    asm("mapa.shared::cluster.u32 %0, %1, %2;" : "=r"(r_mbp0) : "r"(mbp0), "r"(peer));
    asm("mapa.shared::cluster.u32 %0, %1, %2;" : "=r"(r_mbp1) : "r"(mbp1), "r"(peer));

    float c_reg = 0.0f, ac = 0.0f;
    u32 ph_h0 = 0, ph_h1 = 0, ph_s0 = 0, ph_s1 = 0, ph_p0 = 0, ph_p1 = 0;

    // weights: thread (row = tid&255, colhalf = tid>>8). colhalf 0 = LOCAL cols.
    ulonglong2 wc[16];
    float gxv = 0.0f;
    int row = 0, half = 0, colbase = 0, grow = 0;
    if (tid < 512) {
        row = tid & 255;
        half = tid >> 8;                                  // 0: local cols, 1: peer cols
        colbase = (half ? (int)peer : (int)rank) * 64;    // in floats
        grow = ((row >> 6) << 7) + (int)rank * 64 + (row & 63);  // global W row
        const ulonglong2* wp = (const ulonglong2*)g_whp;
        int cb4 = colbase >> 2;
#pragma unroll
        for (int k4 = 0; k4 < 16; k4++) wc[k4] = wp[(cb4 + k4) * 512 + grow];
        if (half == 0) gxv = gxb[grow];                   // gx folded into local-half partial
    }

    __syncthreads();
    asm volatile("barrier.cluster.arrive.aligned;" ::: "memory");
    asm volatile("barrier.cluster.wait.aligned;"   ::: "memory");

    for (int i = 0; i < TT; i++) {
        int p = i & 1;

        if (tid < 512) {
            // peer-col threads wait for peer's hf half (256B); step 0 primed by zeros
            if (half == 1 && i > 0) {
                if (p) { mbar_wait(mbh1, ph_h1); ph_h1 ^= 1u; }
                else   { mbar_wait(mbh0, ph_h0); ph_h0 ^= 1u; }
            }
            const ulonglong2* h2 = (const ulonglong2*)&h_sh[p][colbase];
            u64 a0 = 0ull, a1 = 0ull, a2 = 0ull, a3 = 0ull;
#pragma unroll
            for (int k4 = 0; k4 < 16; k4++) {
                ulonglong2 w = wc[k4];
                ulonglong2 hv = h2[k4];
                if (k4 & 1) { a2 = ffma2(w.x, hv.x, a2); a3 = ffma2(w.y, hv.y, a3); }
                else        { a0 = ffma2(w.x, hv.x, a0); a1 = ffma2(w.y, hv.y, a1); }
            }
            float part = (f2sum(a0) + f2sum(a1)) + (f2sum(a2) + f2sum(a3));
            if (half == 0) {
                part += gxv;
                if (i + 1 < TT) gxv = gxb[(i + 1) * G4 + grow];
            }
            gpart[half][row] = part;
            asm volatile("bar.sync 3, 512;" ::: "memory");   // gates ready

            if (tid < HHF) {
                asm volatile("bar.sync 2, 96;" ::: "memory"); // scheduler results ready
                int j = tid, jg = (int)rank * 64 + j, w = j >> 5;
                int ev = evslot;
                if (ev >= 0) slots[ev][j] = h_sh[p][jg];      // row i = h(i-1)

                float gi = gpart[0][j]        + gpart[1][j];
                float gf = gpart[0][64 + j]   + gpart[1][64 + j];
                float gg = gpart[0][128 + j]  + gpart[1][128 + j];
                float go = gpart[0][192 + j]  + gpart[1][192 + j];
                float ti = fsig(gi), tf = fsig(gf), tg = ftanh(gg), to = fsig(go);
                c_reg = tf * c_reg + ti * tg;
                float hl = to * ftanh(c_reg);

                float wv[5]; int ws[5];
                if (i < 5) {
                    // in-step pa exchange (only first 5 steps)
                    u32 mbp = p ? mbp1 : mbp0;
                    if (j == 0) mbar_expect(mbp, 8u);
                    float pa = ftanh(hl) * wa_s[j];
#pragma unroll
                    for (int o = 16; o; o >>= 1) pa += __shfl_xor_sync(0xffffffffu, pa, o);
                    if (lane == 0) {
                        pasc[p][rank][w] = pa;
                        st_async_f32(r_pas + (((u32)p * 2u + rank) * 2u + (u32)w) * 4u,
                                     pa, p ? r_mbp1 : r_mbp0);
                    }
                    asm volatile("bar.sync 4, 64;" ::: "memory");
                    if (p) { mbar_wait(mbp1, ph_p1); ph_p1 ^= 1u; }
                    else   { mbar_wait(mbp0, ph_p0); ph_p0 ^= 1u; }
                    float ta = (pasc[p][0][0] + pasc[p][0][1]) + (pasc[p][1][0] + pasc[p][1][1]);
                    int rem = i + 1;
#pragma unroll
                    for (int r = 0; r < 5; r++) {
                        if (r < rem) { wv[r] = ta + sb_arr[r]; ws[r] = rowslot[r]; }
                        else         { wv[r] = 0.0f;           ws[r] = 0; }
                    }
                } else {
                    float d = top5v[4] + EPSV;
                    float ssum = 0.0f;
#pragma unroll
                    for (int q = 0; q < 5; q++) {
                        float v = fmaxf(top5v[q] - d, 0.0f);
                        wv[q] = v; ws[q] = top5s[q];
                        ssum += v;
                    }
                    float inv = 1.0f / (ssum + EPSV);
#pragma unroll
                    for (int q = 0; q < 5; q++) wv[q] *= inv;
                }
                ac = 0.0f;
#pragma unroll
                for (int q = 0; q < 5; q++) ac = fmaf(wv[q], slots[ws[q]][j], ac);
                float hf = hl + ac;
                h_sh[p ^ 1][jg] = hf;                          // local half (STS)
                if (i + 1 < TT)
                    st_async_f32(r_hsh + (((u32)(p ^ 1)) * (u32)HH + (u32)jg) * 4u,
                                 hf, p ? r_mbh0 : r_mbh1);     // peer mbar_h[p^1]
                float pb = ftanh(hf) * wb_s[j];
#pragma unroll
                for (int o = 16; o; o >>= 1) pb += __shfl_xor_sync(0xffffffffu, pb, o);
                if (lane == 0) {
                    scal[p ^ 1][rank][w] = pb;
                    if (i + 1 < TT)
                        st_async_f32(r_scl + (((u32)(p ^ 1) * 2u + rank) * 2u + (u32)w) * 4u,
                                     pb, p ? r_mbs0 : r_mbs1);
                }
            }
        } else {
            // ---- scheduler warp: expects for next parity + top-5 maintenance ----
            if (lane == 0) {
                if (i + 1 < TT) {
                    mbar_expect(p ? mbh0 : mbh1, 256u);
                    mbar_expect(p ? mbs0 : mbs1, 8u);
                }
                if (i > 0) {
                    if (p) { mbar_wait(mbs1, ph_s1); ph_s1 ^= 1u; }
                    else   { mbar_wait(mbs0, ph_s0); ph_s0 ^= 1u; }
                    float sbn = (scal[p][0][0] + scal[p][0][1]) + (scal[p][1][0] + scal[p][1][1]);
                    if (i < 5) sb_arr[i] = sbn;
                    if (sbn > top5v[4]) {
                        int evs = top5s[4];
                        int q = 4;
                        while (q > 0 && sbn > top5v[q - 1]) {
                            top5v[q] = top5v[q - 1]; top5r[q] = top5r[q - 1]; top5s[q] = top5s[q - 1];
                            q--;
                        }
                        top5v[q] = sbn; top5r[q] = i; top5s[q] = evs;
                        if (i < 5) rowslot[i] = evs;
                        evslot = evs;
                    } else evslot = -1;
                }
            }
            asm volatile("bar.sync 2, 96;" ::: "memory");
        }
        __syncthreads();  // step boundary
    }

    // ---- epilogue ----
    if (tid < HHF) out_c[b * HH + (int)rank * 64 + tid] = ac;   // each CTA writes its half
    if (rank == 0 && tid == 0) {
        float d = top5v[4] + EPSV;
        float ssum = 0.0f, v[5];
#pragma unroll
        for (int q = 0; q < 5; q++) { v[q] = fmaxf(top5v[q] - d, 0.0f); ssum += v[q]; }
        float inv = 1.0f / (ssum + EPSV);
#pragma unroll
        for (int q = 0; q < 5; q++)
            if (v[q] > 0.0f) out_w[b * TT + top5r[q]] = v[q] * inv;
    }
    asm volatile("barrier.cluster.arrive.aligned;" ::: "memory");
    asm volatile("barrier.cluster.wait.aligned;"   ::: "memory");
}

extern "C" void kernel_launch(void* const* d_in, const int* in_sizes, int n_in,
                              void* d_out, int out_size) {
    const float* x    = (const float*)d_in[0];
    const float* W_ih = (const float*)d_in[1];
    const float* W_hh = (const float*)d_in[2];
    const float* b_ih = (const float*)d_in[3];
    const float* b_hh = (const float*)d_in[4];
    const float* w_t  = (const float*)d_in[5];
    float* out = (float*)d_out;

    gxpack_kernel<<<dim3(BB, TT / 16), 512>>>(x, W_ih, W_hh, b_ih, b_hh);

    cudaLaunchConfig_t cfg = {};
    cfg.gridDim  = dim3(2 * BB, 1, 1);   // 32 clusters x 2 CTAs, one batch row each
    cfg.blockDim = dim3(544, 1, 1);
    cfg.dynamicSmemBytes = 0;
    cfg.stream = 0;
    cudaLaunchAttribute attrs[1];
    attrs[0].id = cudaLaunchAttributeClusterDimension;
    attrs[0].val.clusterDim.x = 2;
    attrs[0].val.clusterDim.y = 1;
    attrs[0].val.clusterDim.z = 1;
    cfg.attrs = attrs;
    cfg.numAttrs = 1;
    cudaLaunchKernelEx(&cfg, rec_kernel, w_t, out);
}

// round 15
// speedup vs baseline: 1.3199x; 1.1290x over previous
#include <cuda_runtime.h>
#include <stdint.h>
#include <math.h>

#define BB 32
#define TT 256
#define INS 64
#define HH 128
#define G4 512
#define EPSV 1e-7f
#define NC 4              // CTAs per cluster (k-split quarters)

typedef unsigned long long u64;
typedef unsigned int u32;

// ---- static device scratch (no cudaMalloc allowed) ----
__device__ __align__(16) u64 g_whp[32 * 512 * 2];   // W_hh packed: [k4][row] -> float4 as 2x u64
__device__ float g_gx[BB * TT * G4];                // precomputed input gate contributions

__device__ __forceinline__ u64 ffma2(u64 a, u64 b, u64 c) {
    u64 d;
    asm("fma.rn.f32x2 %0, %1, %2, %3;" : "=l"(d) : "l"(a), "l"(b), "l"(c));
    return d;
}
__device__ __forceinline__ float f2sum(u64 v) {
    float2 f = *reinterpret_cast<float2*>(&v);
    return f.x + f.y;
}
// accuracy-safe nonlinearities (tanh.approx fails the attn_w check: R10)
__device__ __forceinline__ float fsig(float x)  { return 1.0f / (1.0f + __expf(-x)); }
__device__ __forceinline__ float ftanh(float x) { return 2.0f / (1.0f + __expf(-2.0f * x)) - 1.0f; }

__device__ __forceinline__ u32 smem_u32(const void* p) {
    u32 a;
    asm("{ .reg .u64 t; cvta.to.shared.u64 t, %1; cvt.u32.u64 %0, t; }" : "=r"(a) : "l"(p));
    return a;
}

__device__ __forceinline__ void mbar_wait(u32 mb, u32 parity) {
    asm volatile(
        "{\n\t"
        ".reg .pred P;\n\t"
        "WL_%=:\n\t"
        "mbarrier.try_wait.parity.acquire.cta.shared::cta.b64 P, [%0], %1, 0x989680;\n\t"
        "@P bra.uni WD_%=;\n\t"
        "bra.uni WL_%=;\n\t"
        "WD_%=:\n\t"
        "}"
        :: "r"(mb), "r"(parity) : "memory");
}
__device__ __forceinline__ void st_async_f32(u32 addr, float v, u32 mb) {
    asm volatile("st.async.shared::cluster.mbarrier::complete_tx::bytes.f32 [%0], %1, [%2];"
                 :: "r"(addr), "f"(v), "r"(mb) : "memory");
}

// ---------------- fused pack + gx kernel ----------------
__global__ __launch_bounds__(512) void gxpack_kernel(const float* __restrict__ x,
                                                     const float* __restrict__ W_ih,
                                                     const float* __restrict__ W_hh,
                                                     const float* __restrict__ b_ih,
                                                     const float* __restrict__ b_hh) {
    int b = blockIdx.x, ty = blockIdx.y, j = threadIdx.x;

    if (ty == 0) {
        float* whp = (float*)g_whp;
        for (int idx = b * 512 + j; idx < G4 * HH; idx += 32 * 512) {
            int r = idx >> 7, k = idx & 127;
            whp[((k >> 2) * 512 + r) * 4 + (k & 3)] = W_hh[idx];
        }
    }

    __shared__ float xs[16][INS];
    int t0 = ty * 16;
    for (int idx = j; idx < 16 * INS; idx += 512)
        xs[idx >> 6][idx & 63] = x[(b * TT + t0 + (idx >> 6)) * INS + (idx & 63)];

    float4 w[16];
    const float4* wr = (const float4*)(W_ih + j * INS);
#pragma unroll
    for (int k4 = 0; k4 < 16; k4++) w[k4] = wr[k4];
    float bs = b_ih[j] + b_hh[j];
    __syncthreads();

    for (int tt = 0; tt < 16; tt++) {
        float acc = bs;
#pragma unroll
        for (int k4 = 0; k4 < 16; k4++) {
            acc = fmaf(w[k4].x, xs[tt][4 * k4 + 0], acc);
            acc = fmaf(w[k4].y, xs[tt][4 * k4 + 1], acc);
            acc = fmaf(w[k4].z, xs[tt][4 * k4 + 2], acc);
            acc = fmaf(w[k4].w, xs[tt][4 * k4 + 3], acc);
        }
        g_gx[(b * TT + t0 + tt) * G4 + j] = acc;
    }
}

// ---------------- recurrent kernel: cluster of 4 CTAs per batch row ----------------
// CTA rank r handles k-quarter r (32 cols, 8 ulonglong2 = 16 regs/thread) of the
// 512x128 GEMV. Partials broadcast all-to-all via st.async (4 dsts, tx-counted on
// each dst's parity mbar, expect 8192B). Tail + top-5 fully replicated per CTA
// (no return trip). Warp 16 = scheduler.
__global__ __launch_bounds__(544) void rec_kernel(const float* __restrict__ w_t,
                                                  float* __restrict__ out) {
    int tid = threadIdx.x, lane = tid & 31, wrp = tid >> 5;
    int b = blockIdx.x >> 2;

    u32 rank;
    asm("mov.u32 %0, %%cluster_ctarank;" : "=r"(rank));

    __shared__ __align__(16) float h_sh[HH];
    __shared__ float gpart[2][NC][G4];             // [parity][kquarter][gate] (16 KB)
    __shared__ float pbv[HH];
    __shared__ __align__(16) float slots[5][HH];
    __shared__ float redA[4];
    __shared__ float sb_arr[8];
    __shared__ float top5v[5];
    __shared__ int   top5r[5], top5s[5], rowslot[5], evslot;
    __shared__ float wa_s[HH], wb_s[HH];
    __shared__ __align__(8) u64 mbar[2];

    float* out_c = out;             // [B,H]
    float* out_w = out + BB * HH;   // [B,T]
    const float* gxb = g_gx + (size_t)b * TT * G4;

    if (tid < HH) {
        h_sh[tid] = 0.0f;
        slots[0][tid] = 0.0f;
        wa_s[tid] = w_t[tid];
        wb_s[tid] = w_t[HH + tid];
    }
    if (tid == 0) {
        sb_arr[0] = 0.0f;
        top5v[0] = 0.0f; top5r[0] = 0; top5s[0] = 0;
        for (int q = 1; q < 5; q++) { top5v[q] = -1e30f; top5r[q] = -1; top5s[q] = q; }
        rowslot[0] = 0;
        evslot = -1;
        asm volatile("mbarrier.init.shared.b64 [%0], 1;" :: "r"(smem_u32(&mbar[0])) : "memory");
        asm volatile("mbarrier.init.shared.b64 [%0], 1;" :: "r"(smem_u32(&mbar[1])) : "memory");
    }
    if (rank == 0 && tid < TT) out_w[b * TT + tid] = 0.0f;

    // destination addresses in all 4 CTAs: gpart[0][myrank][0] and mbar[0]
    u32 mbl = smem_u32(&mbar[0]);
    u32 gll = smem_u32(&gpart[0][rank][0]);
    u32 dg[NC], dm[NC];
#pragma unroll
    for (int r = 0; r < NC; r++) {
        asm("mapa.shared::cluster.u32 %0, %1, %2;" : "=r"(dg[r]) : "r"(gll), "r"((u32)r));
        asm("mapa.shared::cluster.u32 %0, %1, %2;" : "=r"(dm[r]) : "r"(mbl), "r"((u32)r));
    }

    float c_reg = 0.0f;
    float ac = 0.0f;
    u32 ph0 = 0, ph1 = 0;

    // this CTA's W_hh quarter: rows = gate (tid), cols = [rank*32, rank*32+32)
    ulonglong2 wc[8];
    float gxv = 0.0f;
    if (tid < 512) {
        const ulonglong2* wp = (const ulonglong2*)g_whp;
#pragma unroll
        for (int k4 = 0; k4 < 8; k4++) wc[k4] = wp[((int)rank * 8 + k4) * 512 + tid];
        if (rank == 0) gxv = gxb[tid];   // gx folded into rank-0 partial
    }

    __syncthreads();
    asm volatile("barrier.cluster.arrive.aligned;" ::: "memory");
    asm volatile("barrier.cluster.wait.aligned;"   ::: "memory");

    for (int i = 0; i < TT; i++) {
        int p = i & 1;
        u32 poff = (u32)p * (u32)(NC * G4 * 4);   // parity offset in gpart
        u32 moff = (u32)p * 8u;                   // parity offset in mbar

        if (tid < 512) {
            // ---- GEMV quarter (register weights); rank 0 adds gx ----
            const ulonglong2* h2 = (const ulonglong2*)h_sh;
            u64 a0 = 0ull, a1 = 0ull, a2 = 0ull, a3 = 0ull;
#pragma unroll
            for (int k4 = 0; k4 < 8; k4++) {
                ulonglong2 w = wc[k4];
                ulonglong2 hv = h2[(int)rank * 8 + k4];
                if (k4 & 1) { a2 = ffma2(w.x, hv.x, a2); a3 = ffma2(w.y, hv.y, a3); }
                else        { a0 = ffma2(w.x, hv.x, a0); a1 = ffma2(w.y, hv.y, a1); }
            }
            float part = gxv + (f2sum(a0) + f2sum(a1)) + (f2sum(a2) + f2sum(a3));
            if (rank == 0 && i + 1 < TT) gxv = gxb[(i + 1) * G4 + tid];  // prefetch

            // broadcast partial to all 4 CTAs (each dst's mbar tx-counts it)
            u32 toff = poff + tid * 4u;
#pragma unroll
            for (int r = 0; r < NC; r++)
                st_async_f32(dg[r] + toff, part, dm[r] + moff);

            if (tid < HH) {
                // overlap DSMEM RTT: sync with scheduler warp, insert evicted slot
                asm volatile("bar.sync 2, 160;" ::: "memory");
                int ev = evslot;
                if (ev >= 0) slots[ev][tid] = h_sh[tid];   // row i = h(i-1)

                // wait for all 8192 bytes of partials
                if (p) { mbar_wait(mbl + 8u, ph1); ph1 ^= 1u; }
                else   { mbar_wait(mbl,      ph0); ph0 ^= 1u; }

                // gates = sum of 4 k-quarters
                float gi = gpart[p][0][tid]          + gpart[p][1][tid]
                         + gpart[p][2][tid]          + gpart[p][3][tid];
                float gf = gpart[p][0][HH + tid]     + gpart[p][1][HH + tid]
                         + gpart[p][2][HH + tid]     + gpart[p][3][HH + tid];
                float gg = gpart[p][0][2*HH + tid]   + gpart[p][1][2*HH + tid]
                         + gpart[p][2][2*HH + tid]   + gpart[p][3][2*HH + tid];
                float go = gpart[p][0][3*HH + tid]   + gpart[p][1][3*HH + tid]
                         + gpart[p][2][3*HH + tid]   + gpart[p][3][3*HH + tid];
                float ti = fsig(gi), tf = fsig(gf), tg = ftanh(gg), to = fsig(go);
                c_reg = tf * c_reg + ti * tg;
                float hl = to * ftanh(c_reg);

                float wv[5]; int ws[5];
                if (i < 5) {
                    // ta needed only while rem<=5 (raw unnormalized scores)
                    float pa = ftanh(hl) * wa_s[tid];
#pragma unroll
                    for (int o = 16; o; o >>= 1) pa += __shfl_xor_sync(0xffffffffu, pa, o);
                    if (lane == 0) redA[wrp] = pa;
                    asm volatile("bar.sync 1, 128;" ::: "memory");
                    float ta = redA[0] + redA[1] + redA[2] + redA[3];
                    int rem = i + 1;
#pragma unroll
                    for (int r = 0; r < 5; r++) {
                        if (r < rem) { wv[r] = ta + sb_arr[r]; ws[r] = rowslot[r]; }
                        else         { wv[r] = 0.0f;           ws[r] = 0; }
                    }
                } else {
                    // ta cancels in the clipped-sparse path
                    float d = top5v[4] + EPSV;
                    float ssum = 0.0f;
#pragma unroll
                    for (int q = 0; q < 5; q++) {
                        float v = fmaxf(top5v[q] - d, 0.0f);
                        wv[q] = v; ws[q] = top5s[q];
                        ssum += v;
                    }
                    float inv = 1.0f / (ssum + EPSV);
#pragma unroll
                    for (int q = 0; q < 5; q++) wv[q] *= inv;
                }
                ac = 0.0f;
#pragma unroll
                for (int q = 0; q < 5; q++) ac = fmaf(wv[q], slots[ws[q]][tid], ac);
                float hf = hl + ac;
                h_sh[tid] = hf;
                pbv[tid] = ftanh(hf) * wb_s[tid];   // reduced by warp 16 next step
            }
        } else {
            // ---- warp 16: expect_tx + top-5 maintenance (overlaps GEMV) ----
            if (lane == 0) {
                asm volatile("mbarrier.arrive.expect_tx.shared.b64 _, [%0], %1;"
                             :: "r"(mbl + moff), "r"((u32)(NC * G4 * 4)) : "memory");
            }
            if (i > 0) {
                float s = pbv[lane] + pbv[lane + 32] + pbv[lane + 64] + pbv[lane + 96];
#pragma unroll
                for (int o = 16; o; o >>= 1) s += __shfl_xor_sync(0xffffffffu, s, o);
                if (lane == 0) {
                    float sbn = s;
                    if (i < 5) sb_arr[i] = sbn;
                    if (sbn > top5v[4]) {
                        int evs = top5s[4];
                        int q = 4;
                        while (q > 0 && sbn > top5v[q - 1]) {
                            top5v[q] = top5v[q - 1]; top5r[q] = top5r[q - 1]; top5s[q] = top5s[q - 1];
                            q--;
                        }
                        top5v[q] = sbn; top5r[q] = i; top5s[q] = evs;
                        if (i < 5) rowslot[i] = evs;
                        evslot = evs;
                    } else evslot = -1;
                }
            }
            asm volatile("bar.sync 2, 160;" ::: "memory");
        }
        __syncthreads();  // step boundary: h_sh/pbv stable for next step
    }

    // ---- epilogue (rank 0 only; results replicated in every CTA) ----
    if (rank == 0) {
        if (tid < HH) out_c[b * HH + tid] = ac;
        if (tid == 0) {
            float d = top5v[4] + EPSV;
            float ssum = 0.0f, v[5];
#pragma unroll
            for (int q = 0; q < 5; q++) { v[q] = fmaxf(top5v[q] - d, 0.0f); ssum += v[q]; }
            float inv = 1.0f / (ssum + EPSV);
#pragma unroll
            for (int q = 0; q < 5; q++)
                if (v[q] > 0.0f) out_w[b * TT + top5r[q]] = v[q] * inv;
        }
    }
    asm volatile("barrier.cluster.arrive.aligned;" ::: "memory");
    asm volatile("barrier.cluster.wait.aligned;"   ::: "memory");
}

extern "C" void kernel_launch(void* const* d_in, const int* in_sizes, int n_in,
                              void* d_out, int out_size) {
    const float* x    = (const float*)d_in[0];
    const float* W_ih = (const float*)d_in[1];
    const float* W_hh = (const float*)d_in[2];
    const float* b_ih = (const float*)d_in[3];
    const float* b_hh = (const float*)d_in[4];
    const float* w_t  = (const float*)d_in[5];
    float* out = (float*)d_out;

    gxpack_kernel<<<dim3(BB, TT / 16), 512>>>(x, W_ih, W_hh, b_ih, b_hh);

    cudaLaunchConfig_t cfg = {};
    cfg.gridDim  = dim3(NC * BB, 1, 1);   // 32 clusters x 4 CTAs, one batch row each
    cfg.blockDim = dim3(544, 1, 1);
    cfg.dynamicSmemBytes = 0;
    cfg.stream = 0;
    cudaLaunchAttribute attrs[1];
    attrs[0].id = cudaLaunchAttributeClusterDimension;
    attrs[0].val.clusterDim.x = NC;
    attrs[0].val.clusterDim.y = 1;
    attrs[0].val.clusterDim.z = 1;
    cfg.attrs = attrs;
    cfg.numAttrs = 1;
    cudaLaunchKernelEx(&cfg, rec_kernel, w_t, out);
}